// round 8
// baseline (speedup 1.0000x reference)
#include <cuda_runtime.h>
#include <cuda_bf16.h>
#include <cstdint>

// GraphConv: out = segment_sum(x[src])@Wn^T + b_n + x@Wr^T + b_r
// y = x@Wn^T ; out = x@Wr^T + (b_n+b_r) ; then out[dst] += y[src] via
// dst-binning (no bulk atomics): bins of 32 slots/node + warp-per-node gather.
// GEMM: fused dual mma.sync m16n8k16 bf16 hi/lo (D = Ah*Bh + Ah*Bl + Al*Bh).

#define N_FEAT 128
#define BM 128
#define BN 256
#define KDIM 128
#define SSTRIDE 136            // bf16 / row: 128 + 8 pad (conflict-free ldmatrix)
#define MAXN 100000
#define BIN_CAP 32

__device__ float g_y[MAXN * N_FEAT];        // x @ Wn^T
__device__ int   g_count[MAXN];             // per-dst edge count
__device__ int   g_bins[MAXN * BIN_CAP];    // src ids binned by dst

__device__ __forceinline__ uint32_t smem_u32(const void* p) {
    uint32_t a;
    asm("{ .reg .u64 t; cvta.to.shared.u64 t, %1; cvt.u32.u64 %0, t; }" : "=r"(a) : "l"(p));
    return a;
}

#define LDMATRIX_X4(r0, r1, r2, r3, addr) \
    asm volatile("ldmatrix.sync.aligned.m8n8.x4.shared.b16 {%0,%1,%2,%3}, [%4];" \
                 : "=r"(r0), "=r"(r1), "=r"(r2), "=r"(r3) : "r"(addr))

#define MMA_BF16(c0, c1, c2, c3, a0, a1, a2, a3, b0, b1) \
    asm volatile("mma.sync.aligned.m16n8k16.row.col.f32.bf16.bf16.f32 " \
                 "{%0,%1,%2,%3}, {%4,%5,%6,%7}, {%8,%9}, {%0,%1,%2,%3};" \
                 : "+f"(c0), "+f"(c1), "+f"(c2), "+f"(c3) \
                 : "r"(a0), "r"(a1), "r"(a2), "r"(a3), "r"(b0), "r"(b1))

// ---------------------------------------------------------------------------
// Fused dual GEMM: C[128 x 256] per CTA. cols 0-127 -> out (+bn+br),
// cols 128-255 -> g_y.  512 threads, 16 warps (4x4), warp tile 32 x 64.
// ---------------------------------------------------------------------------
__global__ void __launch_bounds__(512, 1)
gemm_mma_kernel(const float* __restrict__ x,
                const float* __restrict__ Wn,
                const float* __restrict__ bn,
                const float* __restrict__ Wr,
                const float* __restrict__ br,
                float* __restrict__ out,
                int N)
{
    extern __shared__ __nv_bfloat16 smem[];
    __nv_bfloat16* Ah = smem;                         // [128][SSTRIDE]
    __nv_bfloat16* Al = Ah + BM * SSTRIDE;
    __nv_bfloat16* Bh = Al + BM * SSTRIDE;            // [256 n][SSTRIDE k]
    __nv_bfloat16* Bl = Bh + BN * SSTRIDE;
    __shared__ float bias_s[N_FEAT];

    const int tid = threadIdx.x;
    const int wid = tid >> 5, lane = tid & 31;
    const int wm = wid >> 2;        // 0..3 -> rows wm*32..+31
    const int wn = wid & 3;         // 0..3 -> cols wn*64..+63
    const int mBase = blockIdx.x * BM;

    if (tid < N_FEAT) bias_s[tid] = __ldg(&bn[tid]) + __ldg(&br[tid]);

    // ---- A tile (x) hi/lo: 128 rows x 32 float4 = 4096, 512 thr -> 8 each ----
    #pragma unroll
    for (int it = 0; it < 8; it++) {
        int idx = tid + it * 512;
        int r = idx >> 5, c4 = idx & 31, k0 = c4 * 4;
        float4 v = make_float4(0.f, 0.f, 0.f, 0.f);
        if (mBase + r < N)
            v = reinterpret_cast<const float4*>(x + (size_t)(mBase + r) * N_FEAT)[c4];
        #pragma unroll
        for (int h = 0; h < 2; h++) {
            float f0 = h ? v.z : v.x, f1 = h ? v.w : v.y;
            __nv_bfloat162 hi, lo;
            hi.x = __float2bfloat16(f0); hi.y = __float2bfloat16(f1);
            lo.x = __float2bfloat16(f0 - __bfloat162float(hi.x));
            lo.y = __float2bfloat16(f1 - __bfloat162float(hi.y));
            int o = r * SSTRIDE + k0 + h * 2;
            *reinterpret_cast<__nv_bfloat162*>(Ah + o) = hi;
            *reinterpret_cast<__nv_bfloat162*>(Al + o) = lo;
        }
    }
    // ---- B (both weights) hi/lo: rows 0-127 Wr, 128-255 Wn: 8192 f4 -> 16 each ----
    #pragma unroll
    for (int it = 0; it < 16; it++) {
        int idx = tid + it * 512;
        int r = idx >> 5, c4 = idx & 31, k0 = c4 * 4;
        const float* Wrow = (r < 128) ? (Wr + (size_t)r * N_FEAT)
                                      : (Wn + (size_t)(r - 128) * N_FEAT);
        float4 v = reinterpret_cast<const float4*>(Wrow)[c4];
        #pragma unroll
        for (int h = 0; h < 2; h++) {
            float f0 = h ? v.z : v.x, f1 = h ? v.w : v.y;
            __nv_bfloat162 hi, lo;
            hi.x = __float2bfloat16(f0); hi.y = __float2bfloat16(f1);
            lo.x = __float2bfloat16(f0 - __bfloat162float(hi.x));
            lo.y = __float2bfloat16(f1 - __bfloat162float(hi.y));
            int o = r * SSTRIDE + k0 + h * 2;
            *reinterpret_cast<__nv_bfloat162*>(Bh + o) = hi;
            *reinterpret_cast<__nv_bfloat162*>(Bl + o) = lo;
        }
    }
    __syncthreads();

    float acc[2][8][4];
    #pragma unroll
    for (int i = 0; i < 2; i++)
        #pragma unroll
        for (int j = 0; j < 8; j++)
            #pragma unroll
            for (int q = 0; q < 4; q++) acc[i][j][q] = 0.f;

    // ldmatrix lane addressing (proven in round 7)
    const int aRow = (lane & 7) + ((lane >> 3) & 1) * 8;
    const int aK   = (lane >> 4) * 8;
    const int bRow = (lane & 7) + (lane >> 4) * 8;
    const int bK   = ((lane >> 3) & 1) * 8;

    const uint32_t sAh = smem_u32(Ah), sAl = smem_u32(Al);
    const uint32_t sBh = smem_u32(Bh), sBl = smem_u32(Bl);

    #pragma unroll
    for (int pass = 0; pass < 3; pass++) {
        const uint32_t aBase = (pass == 2) ? sAl : sAh;
        const uint32_t bBase = (pass == 1) ? sBl : sBh;
        #pragma unroll
        for (int ks = 0; ks < KDIM / 16; ks++) {
            const int k = ks * 16;
            uint32_t a[2][4];
            #pragma unroll
            for (int i = 0; i < 2; i++) {
                int row = wm * 32 + i * 16 + aRow;
                LDMATRIX_X4(a[i][0], a[i][1], a[i][2], a[i][3],
                            aBase + (uint32_t)(row * SSTRIDE + k + aK) * 2);
            }
            uint32_t b[4][4];   // b[j2]: regs {0,1}->n-tile 2*j2, {2,3}->2*j2+1
            #pragma unroll
            for (int j2 = 0; j2 < 4; j2++) {
                int n = wn * 64 + j2 * 16 + bRow;
                LDMATRIX_X4(b[j2][0], b[j2][1], b[j2][2], b[j2][3],
                            bBase + (uint32_t)(n * SSTRIDE + k + bK) * 2);
            }
            #pragma unroll
            for (int i = 0; i < 2; i++)
                #pragma unroll
                for (int j = 0; j < 8; j++)
                    MMA_BF16(acc[i][j][0], acc[i][j][1], acc[i][j][2], acc[i][j][3],
                             a[i][0], a[i][1], a[i][2], a[i][3],
                             b[j >> 1][(j & 1) * 2 + 0], b[j >> 1][(j & 1) * 2 + 1]);
        }
    }

    // ---- epilogue: warp cols wn*64 -> wn<2: out(+bias), wn>=2: g_y ----
    const int g = lane >> 2, t = lane & 3;
    const bool toOut = (wn < 2);
    #pragma unroll
    for (int i = 0; i < 2; i++) {
        int r0 = mBase + wm * 32 + i * 16 + g;
        #pragma unroll
        for (int j = 0; j < 8; j++) {
            int c = wn * 64 + j * 8 + 2 * t;        // 0..255
            if (toOut) {
                float b0 = bias_s[c], b1 = bias_s[c + 1];
                if (r0 < N)
                    *reinterpret_cast<float2*>(out + (size_t)r0 * N_FEAT + c) =
                        make_float2(acc[i][j][0] + b0, acc[i][j][1] + b1);
                if (r0 + 8 < N)
                    *reinterpret_cast<float2*>(out + (size_t)(r0 + 8) * N_FEAT + c) =
                        make_float2(acc[i][j][2] + b0, acc[i][j][3] + b1);
            } else {
                int cy = c - 128;
                if (r0 < N)
                    *reinterpret_cast<float2*>(g_y + (size_t)r0 * N_FEAT + cy) =
                        make_float2(acc[i][j][0], acc[i][j][1]);
                if (r0 + 8 < N)
                    *reinterpret_cast<float2*>(g_y + (size_t)(r0 + 8) * N_FEAT + cy) =
                        make_float2(acc[i][j][2], acc[i][j][3]);
            }
        }
    }
}

// ---------------------------------------------------------------------------
__global__ void zero_counts(int n)
{
    int i = blockIdx.x * blockDim.x + threadIdx.x;
    if (i < n) g_count[i] = 0;
}

// Fill bins: one thread per edge. Overflow (slot>=BIN_CAP, p~1e-11) falls back
// to direct red on out (safe: runs after GEMM, before gather).
__global__ void __launch_bounds__(256)
fill_bins_kernel(const void* __restrict__ ei_raw,
                 float* __restrict__ out,
                 int E, int N)
{
    const int e = blockIdx.x * 256 + threadIdx.x;
    const int lane = threadIdx.x & 31;

    const long long* ei64 = (const long long*)ei_raw;
    const int*       ei32 = (const int*)ei_raw;
    long long probe = (lane < 8) ? __ldg(&ei64[lane]) : 0;
    bool ok = (lane < 8) ? (probe >= 0 && probe < (long long)N) : true;
    const bool is64 = ((__ballot_sync(0xFFFFFFFFu, ok) & 0xFFu) == 0xFFu);

    if (e >= E) return;
    long long src, dst;
    if (is64) { src = __ldg(&ei64[e]); dst = __ldg(&ei64[E + e]); }
    else      { src = __ldg(&ei32[e]); dst = __ldg(&ei32[E + e]); }

    long long nmax = (long long)N - 1;
    src = src < 0 ? 0 : (src > nmax ? nmax : src);
    dst = dst < 0 ? 0 : (dst > nmax ? nmax : dst);

    int slot = atomicAdd(&g_count[(int)dst], 1);
    if (slot < BIN_CAP) {
        g_bins[(int)dst * BIN_CAP + slot] = (int)src;
    } else {
        // rare fallback: direct vector reductions
        const float* yp = g_y + (size_t)src * N_FEAT;
        float* op = out + (size_t)dst * N_FEAT;
        #pragma unroll
        for (int q = 0; q < 32; q++) {
            float4 v = reinterpret_cast<const float4*>(yp)[q];
            asm volatile("red.global.add.v4.f32 [%0], {%1, %2, %3, %4};"
                         :: "l"(op + q * 4), "f"(v.x), "f"(v.y), "f"(v.z), "f"(v.w)
                         : "memory");
        }
    }
}

// Gather: one warp per dst node. Prefetch <=32 srcs in one coalesced load,
// accumulate float4/lane, single plain read-modify-write to out (warp owns dst).
__global__ void __launch_bounds__(256)
gather_kernel(float* __restrict__ out, int N)
{
    const int dst = blockIdx.x * 8 + (threadIdx.x >> 5);
    if (dst >= N) return;                     // warp-uniform exit
    const int lane = threadIdx.x & 31;

    int cnt = __ldg(&g_count[dst]);           // broadcast load
    if (cnt == 0) return;                     // warp-uniform
    int m = cnt < BIN_CAP ? cnt : BIN_CAP;

    int s = (lane < m) ? __ldg(&g_bins[dst * BIN_CAP + lane]) : 0;

    float4 acc = make_float4(0.f, 0.f, 0.f, 0.f);
    for (int i = 0; i < m; i++) {
        int src = __shfl_sync(0xFFFFFFFFu, s, i);
        float4 v = reinterpret_cast<const float4*>(g_y + (size_t)src * N_FEAT)[lane];
        acc.x += v.x; acc.y += v.y; acc.z += v.z; acc.w += v.w;
    }

    float4* op = reinterpret_cast<float4*>(out + (size_t)dst * N_FEAT) + lane;
    float4 o = *op;
    o.x += acc.x; o.y += acc.y; o.z += acc.z; o.w += acc.w;
    *op = o;
}

// ---------------------------------------------------------------------------
extern "C" void kernel_launch(void* const* d_in, const int* in_sizes, int n_in,
                              void* d_out, int out_size)
{
    const float* x  = (const float*)d_in[0];
    const void*  ei = d_in[1];
    const float* Wn = (const float*)d_in[2];
    const float* bn = (const float*)d_in[3];
    const float* Wr = (const float*)d_in[4];
    const float* br = (const float*)d_in[5];
    float* out = (float*)d_out;

    const int N = in_sizes[0] / N_FEAT;
    const int E = in_sizes[1] / 2;

    const size_t smem_bytes =
        (size_t)(2 * BM * SSTRIDE + 2 * BN * SSTRIDE) * sizeof(__nv_bfloat16); // 208896
    cudaFuncSetAttribute(gemm_mma_kernel,
                         cudaFuncAttributeMaxDynamicSharedMemorySize,
                         (int)smem_bytes);

    zero_counts<<<(N + 1023) / 1024, 1024>>>(N);

    gemm_mma_kernel<<<(N + BM - 1) / BM, 512, smem_bytes>>>(x, Wn, bn, Wr, br, out, N);

    fill_bins_kernel<<<(E + 255) / 256, 256>>>(ei, out, E, N);

    gather_kernel<<<(N + 7) / 8, 256>>>(out, N);
}

// round 9
// speedup vs baseline: 1.0433x; 1.0433x over previous
#include <cuda_runtime.h>
#include <cuda_bf16.h>
#include <cstdint>

// GraphConv: out = segment_sum(x[src])@Wn^T + b_n + x@Wr^T + b_r
// y = x@Wn^T ; out = x@Wr^T + (b_n+b_r) ; out[dst] += y[src] via dst-binning.
// Mega-kernel: GEMM CTAs + fill CTAs in ONE launch (independent work, overlap).
// GEMM: fused dual mma.sync m16n8k16 bf16 hi/lo (D = Ah*Bh + Ah*Bl + Al*Bh).

#define N_FEAT 128
#define BM 128
#define BN 256
#define KDIM 128
#define SSTRIDE 136            // bf16 / row: 128 + 8 pad (conflict-free ldmatrix)
#define MAXN 100000
#define BIN_CAP 32
#define OVF_CAP 2048
#define FILL_CHUNK 512

__device__ float g_y[MAXN * N_FEAT];        // x @ Wn^T
__device__ int   g_count[MAXN];             // per-dst edge count
__device__ int   g_bins[MAXN * BIN_CAP];    // src ids binned by dst
__device__ int   g_ovf_count;
__device__ int2  g_ovf[OVF_CAP];            // (src,dst) overflow edges

__device__ __forceinline__ uint32_t smem_u32(const void* p) {
    uint32_t a;
    asm("{ .reg .u64 t; cvta.to.shared.u64 t, %1; cvt.u32.u64 %0, t; }" : "=r"(a) : "l"(p));
    return a;
}

#define LDMATRIX_X4(r0, r1, r2, r3, addr) \
    asm volatile("ldmatrix.sync.aligned.m8n8.x4.shared.b16 {%0,%1,%2,%3}, [%4];" \
                 : "=r"(r0), "=r"(r1), "=r"(r2), "=r"(r3) : "r"(addr))

#define MMA_BF16(c0, c1, c2, c3, a0, a1, a2, a3, b0, b1) \
    asm volatile("mma.sync.aligned.m16n8k16.row.col.f32.bf16.bf16.f32 " \
                 "{%0,%1,%2,%3}, {%4,%5,%6,%7}, {%8,%9}, {%0,%1,%2,%3};" \
                 : "+f"(c0), "+f"(c1), "+f"(c2), "+f"(c3) \
                 : "r"(a0), "r"(a1), "r"(a2), "r"(a3), "r"(b0), "r"(b1))

// ---------------------------------------------------------------------------
__global__ void zero_counts(int n)
{
    int i = blockIdx.x * blockDim.x + threadIdx.x;
    if (i < n) g_count[i] = 0;
    if (i == 0) g_ovf_count = 0;
}

// ---------------------------------------------------------------------------
// GEMM body: C[128 x 256] per CTA; cols 0-127 -> out (+bias), 128-255 -> g_y.
// 512 threads, 16 warps (4 x 4), warp tile 32 x 64.
// ---------------------------------------------------------------------------
__device__ void gemm_body(const float* __restrict__ x,
                          const float* __restrict__ Wn,
                          const float* __restrict__ bn,
                          const float* __restrict__ Wr,
                          const float* __restrict__ br,
                          float* __restrict__ out,
                          int N, int ctaM,
                          __nv_bfloat16* smem, float* bias_s)
{
    __nv_bfloat16* Ah = smem;
    __nv_bfloat16* Al = Ah + BM * SSTRIDE;
    __nv_bfloat16* Bh = Al + BM * SSTRIDE;
    __nv_bfloat16* Bl = Bh + BN * SSTRIDE;

    const int tid = threadIdx.x;
    const int wid = tid >> 5, lane = tid & 31;
    const int wm = wid >> 2, wn = wid & 3;
    const int mBase = ctaM * BM;

    if (tid < N_FEAT) bias_s[tid] = __ldg(&bn[tid]) + __ldg(&br[tid]);

    #pragma unroll
    for (int it = 0; it < 8; it++) {
        int idx = tid + it * 512;
        int r = idx >> 5, c4 = idx & 31, k0 = c4 * 4;
        float4 v = make_float4(0.f, 0.f, 0.f, 0.f);
        if (mBase + r < N)
            v = reinterpret_cast<const float4*>(x + (size_t)(mBase + r) * N_FEAT)[c4];
        #pragma unroll
        for (int h = 0; h < 2; h++) {
            float f0 = h ? v.z : v.x, f1 = h ? v.w : v.y;
            __nv_bfloat162 hi, lo;
            hi.x = __float2bfloat16(f0); hi.y = __float2bfloat16(f1);
            lo.x = __float2bfloat16(f0 - __bfloat162float(hi.x));
            lo.y = __float2bfloat16(f1 - __bfloat162float(hi.y));
            int o = r * SSTRIDE + k0 + h * 2;
            *reinterpret_cast<__nv_bfloat162*>(Ah + o) = hi;
            *reinterpret_cast<__nv_bfloat162*>(Al + o) = lo;
        }
    }
    #pragma unroll
    for (int it = 0; it < 16; it++) {
        int idx = tid + it * 512;
        int r = idx >> 5, c4 = idx & 31, k0 = c4 * 4;
        const float* Wrow = (r < 128) ? (Wr + (size_t)r * N_FEAT)
                                      : (Wn + (size_t)(r - 128) * N_FEAT);
        float4 v = reinterpret_cast<const float4*>(Wrow)[c4];
        #pragma unroll
        for (int h = 0; h < 2; h++) {
            float f0 = h ? v.z : v.x, f1 = h ? v.w : v.y;
            __nv_bfloat162 hi, lo;
            hi.x = __float2bfloat16(f0); hi.y = __float2bfloat16(f1);
            lo.x = __float2bfloat16(f0 - __bfloat162float(hi.x));
            lo.y = __float2bfloat16(f1 - __bfloat162float(hi.y));
            int o = r * SSTRIDE + k0 + h * 2;
            *reinterpret_cast<__nv_bfloat162*>(Bh + o) = hi;
            *reinterpret_cast<__nv_bfloat162*>(Bl + o) = lo;
        }
    }
    __syncthreads();

    float acc[2][8][4];
    #pragma unroll
    for (int i = 0; i < 2; i++)
        #pragma unroll
        for (int j = 0; j < 8; j++)
            #pragma unroll
            for (int q = 0; q < 4; q++) acc[i][j][q] = 0.f;

    const int aRow = (lane & 7) + ((lane >> 3) & 1) * 8;
    const int aK   = (lane >> 4) * 8;
    const int bRow = (lane & 7) + (lane >> 4) * 8;
    const int bK   = ((lane >> 3) & 1) * 8;

    const uint32_t sAh = smem_u32(Ah), sAl = smem_u32(Al);
    const uint32_t sBh = smem_u32(Bh), sBl = smem_u32(Bl);

    #pragma unroll
    for (int pass = 0; pass < 3; pass++) {
        const uint32_t aBase = (pass == 2) ? sAl : sAh;
        const uint32_t bBase = (pass == 1) ? sBl : sBh;
        #pragma unroll
        for (int ks = 0; ks < KDIM / 16; ks++) {
            const int k = ks * 16;
            uint32_t a[2][4];
            #pragma unroll
            for (int i = 0; i < 2; i++) {
                int row = wm * 32 + i * 16 + aRow;
                LDMATRIX_X4(a[i][0], a[i][1], a[i][2], a[i][3],
                            aBase + (uint32_t)(row * SSTRIDE + k + aK) * 2);
            }
            uint32_t b[4][4];
            #pragma unroll
            for (int j2 = 0; j2 < 4; j2++) {
                int n = wn * 64 + j2 * 16 + bRow;
                LDMATRIX_X4(b[j2][0], b[j2][1], b[j2][2], b[j2][3],
                            bBase + (uint32_t)(n * SSTRIDE + k + bK) * 2);
            }
            #pragma unroll
            for (int i = 0; i < 2; i++)
                #pragma unroll
                for (int j = 0; j < 8; j++)
                    MMA_BF16(acc[i][j][0], acc[i][j][1], acc[i][j][2], acc[i][j][3],
                             a[i][0], a[i][1], a[i][2], a[i][3],
                             b[j >> 1][(j & 1) * 2 + 0], b[j >> 1][(j & 1) * 2 + 1]);
        }
    }

    const int g = lane >> 2, t = lane & 3;
    const bool toOut = (wn < 2);
    #pragma unroll
    for (int i = 0; i < 2; i++) {
        int r0 = mBase + wm * 32 + i * 16 + g;
        #pragma unroll
        for (int j = 0; j < 8; j++) {
            int c = wn * 64 + j * 8 + 2 * t;
            if (toOut) {
                float b0 = bias_s[c], b1 = bias_s[c + 1];
                if (r0 < N)
                    *reinterpret_cast<float2*>(out + (size_t)r0 * N_FEAT + c) =
                        make_float2(acc[i][j][0] + b0, acc[i][j][1] + b1);
                if (r0 + 8 < N)
                    *reinterpret_cast<float2*>(out + (size_t)(r0 + 8) * N_FEAT + c) =
                        make_float2(acc[i][j][2] + b0, acc[i][j][3] + b1);
            } else {
                int cy = c - 128;
                if (r0 < N)
                    *reinterpret_cast<float2*>(g_y + (size_t)r0 * N_FEAT + cy) =
                        make_float2(acc[i][j][0], acc[i][j][1]);
                if (r0 + 8 < N)
                    *reinterpret_cast<float2*>(g_y + (size_t)(r0 + 8) * N_FEAT + cy) =
                        make_float2(acc[i][j][2], acc[i][j][3]);
            }
        }
    }
}

// ---------------------------------------------------------------------------
// Fill body: FILL_CHUNK edges per CTA. Overflow -> deferred list (no out writes;
// GEMM CTAs in the same launch own out).
// ---------------------------------------------------------------------------
__device__ void fill_body(const void* __restrict__ ei_raw, int cta, int E, int N)
{
    const int e = cta * FILL_CHUNK + threadIdx.x;
    const int lane = threadIdx.x & 31;

    const long long* ei64 = (const long long*)ei_raw;
    const int*       ei32 = (const int*)ei_raw;
    long long probe = (lane < 8) ? __ldg(&ei64[lane]) : 0;
    bool ok = (lane < 8) ? (probe >= 0 && probe < (long long)N) : true;
    const bool is64 = ((__ballot_sync(0xFFFFFFFFu, ok) & 0xFFu) == 0xFFu);

    if (e >= E) return;
    long long src, dst;
    if (is64) { src = __ldg(&ei64[e]); dst = __ldg(&ei64[E + e]); }
    else      { src = __ldg(&ei32[e]); dst = __ldg(&ei32[E + e]); }

    long long nmax = (long long)N - 1;
    src = src < 0 ? 0 : (src > nmax ? nmax : src);
    dst = dst < 0 ? 0 : (dst > nmax ? nmax : dst);

    int slot = atomicAdd(&g_count[(int)dst], 1);
    if (slot < BIN_CAP) {
        g_bins[(int)dst * BIN_CAP + slot] = (int)src;
    } else {
        int o = atomicAdd(&g_ovf_count, 1);
        if (o < OVF_CAP) g_ovf[o] = make_int2((int)src, (int)dst);
    }
}

// ---------------------------------------------------------------------------
__global__ void __launch_bounds__(512, 1)
mega_kernel(const float* __restrict__ x,
            const float* __restrict__ Wn,
            const float* __restrict__ bn,
            const float* __restrict__ Wr,
            const float* __restrict__ br,
            float* __restrict__ out,
            const void* __restrict__ ei,
            int N, int E, int gemmCTAs)
{
    extern __shared__ __nv_bfloat16 smem[];
    __shared__ float bias_s[N_FEAT];
    if ((int)blockIdx.x < gemmCTAs)
        gemm_body(x, Wn, bn, Wr, br, out, N, blockIdx.x, smem, bias_s);
    else
        fill_body(ei, blockIdx.x - gemmCTAs, E, N);
}

// ---------------------------------------------------------------------------
// Gather: one warp per dst; unroll x4 for MLP; single rmw to out (warp owns dst).
// ---------------------------------------------------------------------------
__global__ void __launch_bounds__(256)
gather_kernel(float* __restrict__ out, int N)
{
    const int dst = blockIdx.x * 8 + (threadIdx.x >> 5);
    if (dst >= N) return;
    const int lane = threadIdx.x & 31;

    int cnt = __ldg(&g_count[dst]);
    if (cnt == 0) return;
    int m = cnt < BIN_CAP ? cnt : BIN_CAP;

    int s = (lane < m) ? __ldg(&g_bins[dst * BIN_CAP + lane]) : 0;

    float4 acc = make_float4(0.f, 0.f, 0.f, 0.f);
    int i = 0;
    for (; i + 4 <= m; i += 4) {
        int s0 = __shfl_sync(0xFFFFFFFFu, s, i);
        int s1 = __shfl_sync(0xFFFFFFFFu, s, i + 1);
        int s2 = __shfl_sync(0xFFFFFFFFu, s, i + 2);
        int s3 = __shfl_sync(0xFFFFFFFFu, s, i + 3);
        float4 v0 = reinterpret_cast<const float4*>(g_y + (size_t)s0 * N_FEAT)[lane];
        float4 v1 = reinterpret_cast<const float4*>(g_y + (size_t)s1 * N_FEAT)[lane];
        float4 v2 = reinterpret_cast<const float4*>(g_y + (size_t)s2 * N_FEAT)[lane];
        float4 v3 = reinterpret_cast<const float4*>(g_y + (size_t)s3 * N_FEAT)[lane];
        acc.x += (v0.x + v1.x) + (v2.x + v3.x);
        acc.y += (v0.y + v1.y) + (v2.y + v3.y);
        acc.z += (v0.z + v1.z) + (v2.z + v3.z);
        acc.w += (v0.w + v1.w) + (v2.w + v3.w);
    }
    for (; i < m; i++) {
        int si = __shfl_sync(0xFFFFFFFFu, s, i);
        float4 v = reinterpret_cast<const float4*>(g_y + (size_t)si * N_FEAT)[lane];
        acc.x += v.x; acc.y += v.y; acc.z += v.z; acc.w += v.w;
    }

    if (cnt > BIN_CAP) {            // essentially never; warp-uniform
        int ov = __ldg(&g_ovf_count);
        ov = ov < OVF_CAP ? ov : OVF_CAP;
        for (int k = 0; k < ov; k++) {
            int2 p = g_ovf[k];
            if (p.y == dst) {
                float4 v = reinterpret_cast<const float4*>(g_y + (size_t)p.x * N_FEAT)[lane];
                acc.x += v.x; acc.y += v.y; acc.z += v.z; acc.w += v.w;
            }
        }
    }

    float4* op = reinterpret_cast<float4*>(out + (size_t)dst * N_FEAT) + lane;
    float4 o = *op;
    o.x += acc.x; o.y += acc.y; o.z += acc.z; o.w += acc.w;
    *op = o;
}

// ---------------------------------------------------------------------------
extern "C" void kernel_launch(void* const* d_in, const int* in_sizes, int n_in,
                              void* d_out, int out_size)
{
    const float* x  = (const float*)d_in[0];
    const void*  ei = d_in[1];
    const float* Wn = (const float*)d_in[2];
    const float* bn = (const float*)d_in[3];
    const float* Wr = (const float*)d_in[4];
    const float* br = (const float*)d_in[5];
    float* out = (float*)d_out;

    const int N = in_sizes[0] / N_FEAT;
    const int E = in_sizes[1] / 2;

    const size_t smem_bytes =
        (size_t)(2 * BM * SSTRIDE + 2 * BN * SSTRIDE) * sizeof(__nv_bfloat16); // 208896
    cudaFuncSetAttribute(mega_kernel,
                         cudaFuncAttributeMaxDynamicSharedMemorySize,
                         (int)smem_bytes);

    zero_counts<<<(N + 1023) / 1024, 1024>>>(N);

    const int gemmCTAs = (N + BM - 1) / BM;
    const int fillCTAs = (E + FILL_CHUNK - 1) / FILL_CHUNK;
    mega_kernel<<<gemmCTAs + fillCTAs, 512, smem_bytes>>>(
        x, Wn, bn, Wr, br, out, ei, N, E, gemmCTAs);

    gather_kernel<<<(N + 7) / 8, 256>>>(out, N);
}